// round 11
// baseline (speedup 1.0000x reference)
#include <cuda_runtime.h>

// GRU_83906481094863 — v10: v3's k-split structure, pathologies removed.
// B=512, T=1024, D=46, H=128. 128 CTAs x 320 threads, NB=4 batches/CTA.
// 8 gate warps (2/SMSP): warp w owns units u = w*16+(lane&15); lanes 0-15
//   accumulate k in [0,64), lanes 16-31 k in [64,128) reading a FULL h replica
//   at +16-bank offset with IDENTICAL stride -> one base pointer, all offsets
//   compile-time immediates (v3's runtime-stride pointer array caused
//   alu=10.4%). Partials combined with __shfl_down(16); lanes 0-15 apply MUFU
//   nonlinearities (h carried in registers) and store h' to main+replica.
// threads [256,320): aux, prefetch x(t+1). ONE __syncthreads per step.

#define BB 512
#define TT 1024
#define DD 46
#define DP 48
#define HH 128
#define GG 384
#define NB 4
#define NCTA (BB/NB)   // 128
#define NTHR 320
#define NGATE 256

// Shared floats:
//  sW    [0, 49152)        W_hh k-chunk-major: float4 idx (kc*GG + j)
//  sH    [49152, 50176)    h main [2][NB][HH]
//  pad   [50176, 50192)    16 floats -> replica base = +16 banks vs sH
//  sHrep [50192, 51216)    h replica [2][NB][HH] (full copy, stride 128)
//  sX    [51216, 51600)    x [2][NB][DP]
#define OFF_H    49152
#define OFF_HREP 50192
#define OFF_X    51216
#define SMEM_FLOATS 51600
#define SMEM_BYTES  (SMEM_FLOATS * 4)   // 206400

__device__ __forceinline__ void fma2(unsigned long long &d,
                                     unsigned long long a,
                                     unsigned long long b) {
    asm("fma.rn.f32x2 %0, %1, %2, %0;" : "+l"(d) : "l"(a), "l"(b));
}
__device__ __forceinline__ float sum2(unsigned long long v) {
    float lo, hi;
    asm("mov.b64 {%0, %1}, %2;" : "=f"(lo), "=f"(hi) : "l"(v));
    return lo + hi;
}
__device__ __forceinline__ unsigned long long pack2(float lo, float hi) {
    unsigned long long v;
    asm("mov.b64 %0, {%1, %2};" : "=l"(v) : "f"(lo), "f"(hi));
    return v;
}
__device__ __forceinline__ float fast_sig(float x) {
    float e = __expf(-x);
    return __fdividef(1.f, 1.f + e);
}
__device__ __forceinline__ float fast_tanh(float x) {
    x = fminf(15.f, fmaxf(-15.f, x));
    float e = __expf(-2.f * x);
    return __fdividef(1.f - e, 1.f + e);
}

__global__ void __launch_bounds__(NTHR, 1) gru_v10(
    const float* __restrict__ history,  // [B][T][D]
    const float* __restrict__ W_ih,     // [3H][D]
    const float* __restrict__ W_hh,     // [3H][H]
    const float* __restrict__ b_ih,     // [3H]
    const float* __restrict__ b_hh,     // [3H]
    const float* __restrict__ h0,       // [H]
    float* __restrict__ out)            // [B][H]
{
    extern __shared__ float smem[];
    float* sW    = smem;
    float* sH    = smem + OFF_H;      // [2][NB][HH]
    float* sHrep = smem + OFF_HREP;   // [2][NB][HH], +16 banks vs sH
    float* sX    = smem + OFF_X;      // [2][NB][DP]

    const int tid  = threadIdx.x;
    const int b0   = blockIdx.x * NB;
    const int lane = tid & 31;
    const int wid  = tid >> 5;
    const int half = lane >> 4;                 // 0: k<64, 1: k>=64
    const int u    = (wid << 4) + (lane & 15);  // unit (gate warps: wid<8)

    // ---- stage W_hh k-chunk-major ----
    for (int idx = tid; idx < GG * HH; idx += NTHR) {
        int j = idx >> 7, k = idx & 127;
        sW[((k >> 2) * GG + j) * 4 + (k & 3)] = W_hh[idx];
    }
    // ---- h(0): main + full replica ----
    for (int idx = tid; idx < NB * HH; idx += NTHR) {
        float v = h0[idx & 127];
        sH[idx] = v;
        sHrep[idx] = v;
    }
    // ---- zero x pads (both buffers) ----
    if (tid < 16) {
        int buf = tid >> 3, nb = (tid >> 1) & 3, d = DD + (tid & 1);
        sX[buf * (NB * DP) + nb * DP + d] = 0.f;
    }
    // ---- x(0) ----
    for (int idx = tid; idx < NB * DD; idx += NTHR) {
        int nb = idx / DD, d = idx - nb * DD;
        sX[nb * DP + d] = history[(size_t)(b0 + nb) * (TT * DD) + d];
    }

    // ---- gate-thread private state ----
    unsigned long long wih[3][12];          // W_ih half-rows (24 k each)
    float binit[4] = {0.f, 0.f, 0.f, 0.f};  // accum-init biases (half 0 only)
    float hold[NB] = {0.f, 0.f, 0.f, 0.f};  // h carried in writer registers
    if (tid < NGATE) {
        if (half == 0) {
            binit[0] = b_ih[u] + b_hh[u];                // r
            binit[1] = b_ih[u + HH] + b_hh[u + HH];      // z
            binit[2] = b_hh[u + 2 * HH];                 // g_n
            binit[3] = b_ih[u + 2 * HH];                 // x_n
            float h0v = h0[u];
            #pragma unroll
            for (int nb = 0; nb < NB; nb++) hold[nb] = h0v;
        }
        #pragma unroll
        for (int g = 0; g < 3; g++) {
            const int j = g * HH + u;
            #pragma unroll
            for (int p = 0; p < 12; p++) {
                int k0 = half * 24 + 2 * p;
                float f0 = (k0     < DD) ? W_ih[j * DD + k0]     : 0.f;
                float f1 = (k0 + 1 < DD) ? W_ih[j * DD + k0 + 1] : 0.f;
                wih[g][p] = pack2(f0, f1);
            }
        }
    }

    // base pointers: identical stride for both halves -> immediate offsets.
    // half 0 reads sH + k, half 1 reads sHrep + 64 + (k-64); both: base + nb*128 + kc*4
    const float* hbase = smem + OFF_H + half * (OFF_HREP - OFF_H + 64);
    const float* xbase = sX + half * 24;
    const ulonglong2* wbase = (const ulonglong2*)sW + (half * 16) * GG + u;

    __syncthreads();

    for (int t = 0; t < TT; t++) {
        const int cur = t & 1, nxt = cur ^ 1;

        if (tid < NGATE) {
            const float* hc = hbase + cur * (NB * HH);
            const float* xc = xbase + cur * (NB * DP);

            // a0: r total, a1: z total, a2: g_n (hh), an: x_n (ih);
            // biases folded into half-0 init.
            unsigned long long a0[NB], a1[NB], a2[NB], an[NB];
            #pragma unroll
            for (int nb = 0; nb < NB; nb++) {
                a0[nb] = pack2(binit[0], 0.f);
                a1[nb] = pack2(binit[1], 0.f);
                a2[nb] = pack2(binit[2], 0.f);
                an[nb] = pack2(binit[3], 0.f);
            }

            // ---- hh partial dot: 16 local k-chunks, immediate addressing ----
            #pragma unroll 8
            for (int kc = 0; kc < 16; kc++) {
                ulonglong2 w0 = wbase[kc * GG];
                ulonglong2 w1 = wbase[kc * GG + HH];
                ulonglong2 w2 = wbase[kc * GG + 2 * HH];
                ulonglong2 hA = *(const ulonglong2*)(hc + 0 * HH + kc * 4);
                ulonglong2 hB = *(const ulonglong2*)(hc + 1 * HH + kc * 4);
                ulonglong2 hC = *(const ulonglong2*)(hc + 2 * HH + kc * 4);
                ulonglong2 hD = *(const ulonglong2*)(hc + 3 * HH + kc * 4);
                fma2(a0[0], w0.x, hA.x); fma2(a0[0], w0.y, hA.y);
                fma2(a0[1], w0.x, hB.x); fma2(a0[1], w0.y, hB.y);
                fma2(a0[2], w0.x, hC.x); fma2(a0[2], w0.y, hC.y);
                fma2(a0[3], w0.x, hD.x); fma2(a0[3], w0.y, hD.y);
                fma2(a1[0], w1.x, hA.x); fma2(a1[0], w1.y, hA.y);
                fma2(a1[1], w1.x, hB.x); fma2(a1[1], w1.y, hB.y);
                fma2(a1[2], w1.x, hC.x); fma2(a1[2], w1.y, hC.y);
                fma2(a1[3], w1.x, hD.x); fma2(a1[3], w1.y, hD.y);
                fma2(a2[0], w2.x, hA.x); fma2(a2[0], w2.y, hA.y);
                fma2(a2[1], w2.x, hB.x); fma2(a2[1], w2.y, hB.y);
                fma2(a2[2], w2.x, hC.x); fma2(a2[2], w2.y, hC.y);
                fma2(a2[3], w2.x, hD.x); fma2(a2[3], w2.y, hD.y);
            }
            // ---- ih partial dot: 6 local x-chunks; r/z merge into a0/a1 ----
            #pragma unroll
            for (int q = 0; q < 6; q++) {
                ulonglong2 xA = *(const ulonglong2*)(xc + 0 * DP + 4 * q);
                ulonglong2 xB = *(const ulonglong2*)(xc + 1 * DP + 4 * q);
                ulonglong2 xC = *(const ulonglong2*)(xc + 2 * DP + 4 * q);
                ulonglong2 xD = *(const ulonglong2*)(xc + 3 * DP + 4 * q);
                unsigned long long w0a = wih[0][2*q], w0b = wih[0][2*q+1];
                unsigned long long w1a = wih[1][2*q], w1b = wih[1][2*q+1];
                unsigned long long w2a = wih[2][2*q], w2b = wih[2][2*q+1];
                fma2(a0[0], w0a, xA.x); fma2(a0[0], w0b, xA.y);
                fma2(a0[1], w0a, xB.x); fma2(a0[1], w0b, xB.y);
                fma2(a0[2], w0a, xC.x); fma2(a0[2], w0b, xC.y);
                fma2(a0[3], w0a, xD.x); fma2(a0[3], w0b, xD.y);
                fma2(a1[0], w1a, xA.x); fma2(a1[0], w1b, xA.y);
                fma2(a1[1], w1a, xB.x); fma2(a1[1], w1b, xB.y);
                fma2(a1[2], w1a, xC.x); fma2(a1[2], w1b, xC.y);
                fma2(a1[3], w1a, xD.x); fma2(a1[3], w1b, xD.y);
                fma2(an[0], w2a, xA.x); fma2(an[0], w2b, xA.y);
                fma2(an[1], w2a, xB.x); fma2(an[1], w2b, xB.y);
                fma2(an[2], w2a, xC.x); fma2(an[2], w2b, xC.y);
                fma2(an[3], w2a, xD.x); fma2(an[3], w2b, xD.y);
            }

            // ---- combine halves, then finish on lanes 0-15 ----
            float pr[NB], pz[NB], pgn[NB], pxn[NB];
            #pragma unroll
            for (int nb = 0; nb < NB; nb++) {
                pr[nb]  = sum2(a0[nb]);
                pz[nb]  = sum2(a1[nb]);
                pgn[nb] = sum2(a2[nb]);
                pxn[nb] = sum2(an[nb]);
            }
            #pragma unroll
            for (int nb = 0; nb < NB; nb++) {
                pr[nb]  += __shfl_down_sync(0xffffffffu, pr[nb],  16);
                pz[nb]  += __shfl_down_sync(0xffffffffu, pz[nb],  16);
                pgn[nb] += __shfl_down_sync(0xffffffffu, pgn[nb], 16);
                pxn[nb] += __shfl_down_sync(0xffffffffu, pxn[nb], 16);
            }

            if (half == 0) {
                float* hn  = sH    + nxt * (NB * HH);
                float* hnr = sHrep + nxt * (NB * HH);
                #pragma unroll
                for (int nb = 0; nb < NB; nb++) {
                    float r = fast_sig(pr[nb]);
                    float z = fast_sig(pz[nb]);
                    float n = fast_tanh(pxn[nb] + r * pgn[nb]);
                    float hv = n + z * (hold[nb] - n);
                    hold[nb] = hv;
                    hn[nb * HH + u]  = hv;
                    hnr[nb * HH + u] = hv;
                    if (t == TT - 1)
                        out[(size_t)(b0 + nb) * HH + u] = hv;
                }
            }
        } else {
            // ---- aux: prefetch x(t+1) ----
            if (t + 1 < TT) {
                const int a = tid - NGATE;   // 0..63
                #pragma unroll
                for (int r = 0; r < 3; r++) {
                    int idx = a + r * 64;
                    if (idx < NB * DD) {
                        int nb = idx / DD, d = idx - nb * DD;
                        sX[nxt * (NB * DP) + nb * DP + d] =
                            history[(size_t)(b0 + nb) * (TT * DD) + (t + 1) * DD + d];
                    }
                }
            }
        }

        __syncthreads();   // h(t+1) both copies + x(t+1) visible
    }
}

extern "C" void kernel_launch(void* const* d_in, const int* in_sizes, int n_in,
                              void* d_out, int out_size) {
    const float* history = (const float*)d_in[0];
    const float* W_ih    = (const float*)d_in[1];
    const float* W_hh    = (const float*)d_in[2];
    const float* b_ih    = (const float*)d_in[3];
    const float* b_hh    = (const float*)d_in[4];
    const float* h0      = (const float*)d_in[5];
    float* out = (float*)d_out;

    cudaFuncSetAttribute(gru_v10,
                         cudaFuncAttributeMaxDynamicSharedMemorySize, SMEM_BYTES);
    gru_v10<<<NCTA, NTHR, SMEM_BYTES>>>(history, W_ih, W_hh,
                                        b_ih, b_hh, h0, out);
}